// round 5
// baseline (speedup 1.0000x reference)
#include <cuda_runtime.h>

#define NMAX 100000
#define EMAX 2000000
#define SCAN_T 1024

// Scratch (__device__ globals; no allocations allowed)
__device__ __align__(128) float  g_bufA[NMAX * 32];   // layer-1 messages (xw)
__device__ __align__(128) float  g_bufB[NMAX * 32];   // layer-2 messages
__device__ __align__(16)  float2 g_erec[EMAX];        // CSR records {src_as_int, dinv[src]*ew}
__device__ int   g_count[NMAX];
__device__ int   g_rowptr[NMAX + 1];
__device__ int   g_cursor[NMAX];
__device__ float g_deg[NMAX];
__device__ float g_dinv[NMAX];

// ---------------------------------------------------------------------------
// Zero count + deg accumulators
__global__ void zero_kernel(int n) {
    int i = blockIdx.x * blockDim.x + threadIdx.x;
    if (i < n) { g_count[i] = 0; g_deg[i] = 0.0f; }
}

// count[col]++ and deg[col]+=ew, 4 edges per thread
__global__ void countdeg_kernel(const int* __restrict__ col, const float* __restrict__ ew, int E) {
    int t = blockIdx.x * blockDim.x + threadIdx.x;
    int base = t * 4;
    if (base + 3 < E) {
        int4   c4 = *(const int4*)(col + base);
        float4 w4 = *(const float4*)(ew + base);
        atomicAdd(&g_count[c4.x], 1); atomicAdd(&g_deg[c4.x], w4.x);
        atomicAdd(&g_count[c4.y], 1); atomicAdd(&g_deg[c4.y], w4.y);
        atomicAdd(&g_count[c4.z], 1); atomicAdd(&g_deg[c4.z], w4.z);
        atomicAdd(&g_count[c4.w], 1); atomicAdd(&g_deg[c4.w], w4.w);
    } else {
        for (int e = base; e < E; e++) {
            atomicAdd(&g_count[col[e]], 1);
            atomicAdd(&g_deg[col[e]], ew[e]);
        }
    }
}

// Single-block scan: rowptr = exclusive_scan(count); cursor = rowptr;
// also dinv = rsqrt(deg + 1)  (self-loop weight folded in)
__global__ void scan_kernel(int n, int E) {
    __shared__ int spart[SCAN_T];
    int t = threadIdx.x;
    int K = (n + SCAN_T - 1) / SCAN_T;
    int lo = t * K;
    int hi = lo + K; if (hi > n) hi = n;

    int s = 0;
    for (int i = lo; i < hi; i++) s += g_count[i];
    spart[t] = s;
    __syncthreads();
    for (int off = 1; off < SCAN_T; off <<= 1) {
        int v = (t >= off) ? spart[t - off] : 0;
        __syncthreads();
        spart[t] += v;
        __syncthreads();
    }
    int run = spart[t] - s;   // exclusive prefix of this thread's chunk
    for (int i = lo; i < hi; i++) {
        int cnt = g_count[i];
        g_rowptr[i] = run;
        g_cursor[i] = run;
        g_dinv[i]   = rsqrtf(g_deg[i] + 1.0f);
        run += cnt;
    }
    if (t == SCAN_T - 1) g_rowptr[n] = E;
}

// fill CSR: record {src, dinv[src]*ew} bucketed by destination, 4 edges/thread
__global__ void fill_kernel(const int* __restrict__ row, const int* __restrict__ col,
                            const float* __restrict__ ew, int E) {
    int t = blockIdx.x * blockDim.x + threadIdx.x;
    int base = t * 4;
    if (base + 3 < E) {
        int4   r4 = *(const int4*)(row + base);
        int4   c4 = *(const int4*)(col + base);
        float4 w4 = *(const float4*)(ew + base);
        int p0 = atomicAdd(&g_cursor[c4.x], 1);
        int p1 = atomicAdd(&g_cursor[c4.y], 1);
        int p2 = atomicAdd(&g_cursor[c4.z], 1);
        int p3 = atomicAdd(&g_cursor[c4.w], 1);
        g_erec[p0] = make_float2(__int_as_float(r4.x), g_dinv[r4.x] * w4.x);
        g_erec[p1] = make_float2(__int_as_float(r4.y), g_dinv[r4.y] * w4.y);
        g_erec[p2] = make_float2(__int_as_float(r4.z), g_dinv[r4.z] * w4.z);
        g_erec[p3] = make_float2(__int_as_float(r4.w), g_dinv[r4.w] * w4.w);
    } else {
        for (int e = base; e < E; e++) {
            int r = row[e], c = col[e];
            int pos = atomicAdd(&g_cursor[c], 1);
            g_erec[pos] = make_float2(__int_as_float(r), g_dinv[r] * ew[e]);
        }
    }
}

// ---------------------------------------------------------------------------
// Per-node: emb = relu(c@We1+be1)@We2+be2 ; feat=[x,emb] ; bufA = feat@W1
__global__ void embed_kernel(const float* __restrict__ x, const float* __restrict__ c,
                             const float* __restrict__ We1, const float* __restrict__ be1,
                             const float* __restrict__ We2, const float* __restrict__ be2,
                             const float* __restrict__ W1, int n) {
    __shared__ float4 sPack[128];   // {We1[0][j], We1[1][j], be1[j], 0}
    __shared__ float4 sWe2[512];    // [128][16] as float4
    __shared__ float  sbe2[16];
    __shared__ float4 sW1[152];     // [19][32] as float4

    for (int j = threadIdx.x; j < 128; j += blockDim.x)
        sPack[j] = make_float4(We1[j], We1[128 + j], be1[j], 0.f);
    for (int j = threadIdx.x; j < 512; j += blockDim.x)
        sWe2[j] = ((const float4*)We2)[j];
    if (threadIdx.x < 16) sbe2[threadIdx.x] = be2[threadIdx.x];
    for (int j = threadIdx.x; j < 152; j += blockDim.x)
        sW1[j] = ((const float4*)W1)[j];
    __syncthreads();

    int i = blockIdx.x * blockDim.x + threadIdx.x;
    if (i >= n) return;

    float c0 = c[2 * i], c1 = c[2 * i + 1];
    float emb[16];
#pragma unroll
    for (int k = 0; k < 16; k++) emb[k] = sbe2[k];

#pragma unroll 4
    for (int j = 0; j < 128; j++) {
        float4 p = sPack[j];
        float h = fmaxf(fmaf(c0, p.x, fmaf(c1, p.y, p.z)), 0.f);
#pragma unroll
        for (int q = 0; q < 4; q++) {
            float4 w = sWe2[j * 4 + q];
            emb[4 * q + 0] = fmaf(h, w.x, emb[4 * q + 0]);
            emb[4 * q + 1] = fmaf(h, w.y, emb[4 * q + 1]);
            emb[4 * q + 2] = fmaf(h, w.z, emb[4 * q + 2]);
            emb[4 * q + 3] = fmaf(h, w.w, emb[4 * q + 3]);
        }
    }

    float feat[19];
    feat[0] = x[3 * i]; feat[1] = x[3 * i + 1]; feat[2] = x[3 * i + 2];
#pragma unroll
    for (int k = 0; k < 16; k++) feat[3 + k] = emb[k];

    float4 acc[8];
#pragma unroll
    for (int q = 0; q < 8; q++) acc[q] = make_float4(0.f, 0.f, 0.f, 0.f);
#pragma unroll
    for (int r = 0; r < 19; r++) {
        float f = feat[r];
#pragma unroll
        for (int q = 0; q < 8; q++) {
            float4 w = sW1[r * 8 + q];
            acc[q].x = fmaf(f, w.x, acc[q].x);
            acc[q].y = fmaf(f, w.y, acc[q].y);
            acc[q].z = fmaf(f, w.z, acc[q].z);
            acc[q].w = fmaf(f, w.w, acc[q].w);
        }
    }
    float4* outp = (float4*)&g_bufA[(size_t)i * 32];
#pragma unroll
    for (int q = 0; q < 8; q++) outp[q] = acc[q];
}

// ---------------------------------------------------------------------------
// Gather layer 1 (fused mid): one warp per node, lane = column.
// agg = dinv_i * (sum_e val_e * bufA[src_e] + dinv_i * bufA[i])
// h1 = relu(agg + b1); bufB[i] = h1 @ W2   (shfl-broadcast matmul)
__global__ void gather1_kernel(const float* __restrict__ b1, const float* __restrict__ W2, int n) {
    __shared__ float sW2[1024];  // [32][32]
    for (int j = threadIdx.x; j < 1024; j += blockDim.x) sW2[j] = W2[j];
    __syncthreads();

    int warp = (blockIdx.x * blockDim.x + threadIdx.x) >> 5;
    int lane = threadIdx.x & 31;
    if (warp >= n) return;
    int i = warp;

    int start = g_rowptr[i];
    int end   = g_rowptr[i + 1];
    float di  = g_dinv[i];

    float acc = di * g_bufA[(size_t)i * 32 + lane];   // self-loop term (x di below)
    int e = start;
    for (; e + 4 <= end; e += 4) {
        float2 r0 = g_erec[e + 0];
        float2 r1 = g_erec[e + 1];
        float2 r2 = g_erec[e + 2];
        float2 r3 = g_erec[e + 3];
        float v0 = g_bufA[(size_t)__float_as_int(r0.x) * 32 + lane];
        float v1 = g_bufA[(size_t)__float_as_int(r1.x) * 32 + lane];
        float v2 = g_bufA[(size_t)__float_as_int(r2.x) * 32 + lane];
        float v3 = g_bufA[(size_t)__float_as_int(r3.x) * 32 + lane];
        acc = fmaf(r0.y, v0, acc);
        acc = fmaf(r1.y, v1, acc);
        acc = fmaf(r2.y, v2, acc);
        acc = fmaf(r3.y, v3, acc);
    }
    for (; e < end; e++) {
        float2 r = g_erec[e];
        acc = fmaf(r.y, g_bufA[(size_t)__float_as_int(r.x) * 32 + lane], acc);
    }
    acc *= di;

    float h = fmaxf(acc + b1[lane], 0.f);

    float o = 0.f;
#pragma unroll
    for (int m = 0; m < 32; m++) {
        float hm = __shfl_sync(0xffffffffu, h, m);
        o = fmaf(hm, sW2[m * 32 + lane], o);
    }
    g_bufB[(size_t)i * 32 + lane] = o;
}

// ---------------------------------------------------------------------------
// Gather layer 2 (fused final): agg over bufB; h2 = relu(agg + b2);
// out[i] = sum_lane h2 * Wfc + bfc   (warp reduce)
__global__ void gather2_kernel(const float* __restrict__ b2, const float* __restrict__ Wfc,
                               const float* __restrict__ bfc, float* __restrict__ out, int n) {
    int warp = (blockIdx.x * blockDim.x + threadIdx.x) >> 5;
    int lane = threadIdx.x & 31;
    if (warp >= n) return;
    int i = warp;

    int start = g_rowptr[i];
    int end   = g_rowptr[i + 1];
    float di  = g_dinv[i];

    float acc = di * g_bufB[(size_t)i * 32 + lane];
    int e = start;
    for (; e + 4 <= end; e += 4) {
        float2 r0 = g_erec[e + 0];
        float2 r1 = g_erec[e + 1];
        float2 r2 = g_erec[e + 2];
        float2 r3 = g_erec[e + 3];
        float v0 = g_bufB[(size_t)__float_as_int(r0.x) * 32 + lane];
        float v1 = g_bufB[(size_t)__float_as_int(r1.x) * 32 + lane];
        float v2 = g_bufB[(size_t)__float_as_int(r2.x) * 32 + lane];
        float v3 = g_bufB[(size_t)__float_as_int(r3.x) * 32 + lane];
        acc = fmaf(r0.y, v0, acc);
        acc = fmaf(r1.y, v1, acc);
        acc = fmaf(r2.y, v2, acc);
        acc = fmaf(r3.y, v3, acc);
    }
    for (; e < end; e++) {
        float2 r = g_erec[e];
        acc = fmaf(r.y, g_bufB[(size_t)__float_as_int(r.x) * 32 + lane], acc);
    }
    acc *= di;

    float p = fmaxf(acc + b2[lane], 0.f) * Wfc[lane];
#pragma unroll
    for (int off = 16; off > 0; off >>= 1)
        p += __shfl_down_sync(0xffffffffu, p, off);
    if (lane == 0) out[i] = p + bfc[0];
}

// ---------------------------------------------------------------------------
extern "C" void kernel_launch(void* const* d_in, const int* in_sizes, int n_in,
                              void* d_out, int out_size) {
    const float* x   = (const float*)d_in[0];
    const float* c   = (const float*)d_in[1];
    const int*   ei  = (const int*)d_in[2];
    const float* ew  = (const float*)d_in[3];
    const float* We1 = (const float*)d_in[4];
    const float* be1 = (const float*)d_in[5];
    const float* We2 = (const float*)d_in[6];
    const float* be2 = (const float*)d_in[7];
    const float* W1  = (const float*)d_in[8];
    const float* b1  = (const float*)d_in[9];
    const float* W2  = (const float*)d_in[10];
    const float* b2  = (const float*)d_in[11];
    const float* Wfc = (const float*)d_in[12];
    const float* bfc = (const float*)d_in[13];

    int n = in_sizes[1] / 2;   // c is [N, 2]
    int E = in_sizes[3];       // ew is [E]
    const int TB = 256;
    int Et = (E + 3) / 4;      // threads for 4-edges-per-thread kernels

    zero_kernel    <<<(n + TB - 1) / TB, TB>>>(n);
    countdeg_kernel<<<(Et + TB - 1) / TB, TB>>>(ei + E, ew, E);
    scan_kernel    <<<1, SCAN_T>>>(n, E);
    fill_kernel    <<<(Et + TB - 1) / TB, TB>>>(ei, ei + E, ew, E);
    embed_kernel   <<<(n + TB - 1) / TB, TB>>>(x, c, We1, be1, We2, be2, W1, n);

    int gblocks = (n * 32 + TB - 1) / TB;   // one warp per node
    gather1_kernel<<<gblocks, TB>>>(b1, W2, n);
    gather2_kernel<<<gblocks, TB>>>(b2, Wfc, bfc, (float*)d_out, n);
}

// round 7
// speedup vs baseline: 2.6651x; 2.6651x over previous
#include <cuda_runtime.h>

#define NMAX 100000
#define EMAX 2000000
#define FPAD 20            // feat width 19 padded to 20 (5 float4)

// Scratch (__device__ globals; no allocations allowed)
__device__ __align__(128) float g_feat[NMAX * FPAD];  // [x(3), emb(16), pad] per node
__device__ __align__(128) float g_aggF[NMAX * FPAD];  // layer-1 aggregation target (20-wide)
__device__ __align__(128) float g_bufA[NMAX * 32];    // h1@W2 messages for layer 2
__device__ __align__(128) float g_bufB[NMAX * 32];    // layer-2 aggregation target
__device__ float g_deg[NMAX];                         // weighted degree accumulator
__device__ float g_dinv[NMAX];                        // rsqrt(deg+1)

// ---------------------------------------------------------------------------
// Zero 20-wide agg buffer and degree accumulator
__global__ void zero_kernel(int n) {
    int i = blockIdx.x * blockDim.x + threadIdx.x;
    if (i < n * 5) ((float4*)g_aggF)[i] = make_float4(0.f, 0.f, 0.f, 0.f);
    if (i < n) g_deg[i] = 0.0f;
}

// deg[col] += ew, 4 edges per thread (vectorized index/weight loads)
__global__ void deg_kernel(const int* __restrict__ col, const float* __restrict__ ew, int E4) {
    int t = blockIdx.x * blockDim.x + threadIdx.x;
    if (t >= E4) return;
    int4   c4 = ((const int4*)col)[t];
    float4 w4 = ((const float4*)ew)[t];
    atomicAdd(&g_deg[c4.x], w4.x);
    atomicAdd(&g_deg[c4.y], w4.y);
    atomicAdd(&g_deg[c4.z], w4.z);
    atomicAdd(&g_deg[c4.w], w4.w);
}

// ---------------------------------------------------------------------------
// Per-node: dinv = rsqrt(deg+1); emb = relu(c@We1+be1)@We2+be2;
// feat = [x, emb, pad0] -> g_feat (20 floats). W1 is applied AFTER aggregation.
__global__ void embed_kernel(const float* __restrict__ x, const float* __restrict__ c,
                             const float* __restrict__ We1, const float* __restrict__ be1,
                             const float* __restrict__ We2, const float* __restrict__ be2,
                             int n) {
    __shared__ float4 sPack[128];   // {We1[0][j], We1[1][j], be1[j], 0}
    __shared__ float4 sWe2[512];    // [128][16] as float4
    __shared__ float  sbe2[16];

    for (int j = threadIdx.x; j < 128; j += blockDim.x)
        sPack[j] = make_float4(We1[j], We1[128 + j], be1[j], 0.f);
    for (int j = threadIdx.x; j < 512; j += blockDim.x)
        sWe2[j] = ((const float4*)We2)[j];
    if (threadIdx.x < 16) sbe2[threadIdx.x] = be2[threadIdx.x];
    __syncthreads();

    int i = blockIdx.x * blockDim.x + threadIdx.x;
    if (i >= n) return;

    g_dinv[i] = rsqrtf(g_deg[i] + 1.0f);   // self-loop weight 1 folded in

    float c0 = c[2 * i], c1 = c[2 * i + 1];
    float emb[16];
#pragma unroll
    for (int k = 0; k < 16; k++) emb[k] = sbe2[k];

#pragma unroll 4
    for (int j = 0; j < 128; j++) {
        float4 p = sPack[j];
        float h = fmaxf(fmaf(c0, p.x, fmaf(c1, p.y, p.z)), 0.f);
#pragma unroll
        for (int q = 0; q < 4; q++) {
            float4 w = sWe2[j * 4 + q];
            emb[4 * q + 0] = fmaf(h, w.x, emb[4 * q + 0]);
            emb[4 * q + 1] = fmaf(h, w.y, emb[4 * q + 1]);
            emb[4 * q + 2] = fmaf(h, w.z, emb[4 * q + 2]);
            emb[4 * q + 3] = fmaf(h, w.w, emb[4 * q + 3]);
        }
    }

    float4* fp = (float4*)&g_feat[(size_t)i * FPAD];
    fp[0] = make_float4(x[3 * i], x[3 * i + 1], x[3 * i + 2], emb[0]);
    fp[1] = make_float4(emb[1],  emb[2],  emb[3],  emb[4]);
    fp[2] = make_float4(emb[5],  emb[6],  emb[7],  emb[8]);
    fp[3] = make_float4(emb[9],  emb[10], emb[11], emb[12]);
    fp[4] = make_float4(emb[13], emb[14], emb[15], 0.f);
}

// ---------------------------------------------------------------------------
// Scatter layer 1: 5 threads per edge (20-wide feat), float4 chunks.
// aggF[col] += nrm * feat[row], nrm = dinv[r]*ew*dinv[c]  (full norm applied here)
__global__ void scatter1_kernel(const int* __restrict__ ei, const float* __restrict__ ew, int E) {
    int t = blockIdx.x * blockDim.x + threadIdx.x;
    int e = t / 5;
    int q = t - e * 5;
    if (e >= E) return;
    int r = ei[e];
    int c = ei[E + e];
    float nrm = g_dinv[r] * ew[e] * g_dinv[c];
    float4 v = ((const float4*)g_feat)[(size_t)r * 5 + q];
    float vx = v.x * nrm, vy = v.y * nrm, vz = v.z * nrm, vw = v.w * nrm;
    float4* dst = ((float4*)g_aggF) + (size_t)c * 5 + q;
    asm volatile("red.global.add.v4.f32 [%0], {%1,%2,%3,%4};"
                 :: "l"(dst), "f"(vx), "f"(vy), "f"(vz), "f"(vw)
                 : "memory");
}

// ---------------------------------------------------------------------------
// Mid: t = aggF + dinv^2*feat_self  (full norm already in aggF; self-loop norm = dinv^2)
// h1 = relu(t@W1 + b1); bufA = h1@W2; zero bufB for layer-2 scatter.
__global__ void mid_kernel(const float* __restrict__ W1, const float* __restrict__ b1,
                           const float* __restrict__ W2, int n) {
    __shared__ float4 sW1[152];  // [19][32] as float4
    __shared__ float4 sW2[256];  // [32][32] as float4
    __shared__ float  sb1[32];
    for (int j = threadIdx.x; j < 152; j += blockDim.x) sW1[j] = ((const float4*)W1)[j];
    for (int j = threadIdx.x; j < 256; j += blockDim.x) sW2[j] = ((const float4*)W2)[j];
    if (threadIdx.x < 32) sb1[threadIdx.x] = b1[threadIdx.x];
    __syncthreads();

    int i = blockIdx.x * blockDim.x + threadIdx.x;
    if (i >= n) return;

    float d = g_dinv[i];
    float s = d * d;
    const float* aggp = &g_aggF[(size_t)i * FPAD];
    const float* fp   = &g_feat[(size_t)i * FPAD];

    float t[19];
#pragma unroll
    for (int k = 0; k < 19; k++) t[k] = fmaf(s, fp[k], aggp[k]);

    // h1 = relu(t @ W1 + b1)
    float4 acc[8];
#pragma unroll
    for (int q = 0; q < 8; q++) acc[q] = make_float4(sb1[4*q], sb1[4*q+1], sb1[4*q+2], sb1[4*q+3]);
#pragma unroll
    for (int r = 0; r < 19; r++) {
        float f = t[r];
#pragma unroll
        for (int q = 0; q < 8; q++) {
            float4 w = sW1[r * 8 + q];
            acc[q].x = fmaf(f, w.x, acc[q].x);
            acc[q].y = fmaf(f, w.y, acc[q].y);
            acc[q].z = fmaf(f, w.z, acc[q].z);
            acc[q].w = fmaf(f, w.w, acc[q].w);
        }
    }
    float h[32];
#pragma unroll
    for (int q = 0; q < 8; q++) {
        h[4*q+0] = fmaxf(acc[q].x, 0.f);
        h[4*q+1] = fmaxf(acc[q].y, 0.f);
        h[4*q+2] = fmaxf(acc[q].z, 0.f);
        h[4*q+3] = fmaxf(acc[q].w, 0.f);
    }

    // o = h1 @ W2
    float4 o[8];
#pragma unroll
    for (int q = 0; q < 8; q++) o[q] = make_float4(0.f, 0.f, 0.f, 0.f);
#pragma unroll
    for (int m = 0; m < 32; m++) {
        float f = h[m];
#pragma unroll
        for (int q = 0; q < 8; q++) {
            float4 w = sW2[m * 8 + q];
            o[q].x = fmaf(f, w.x, o[q].x);
            o[q].y = fmaf(f, w.y, o[q].y);
            o[q].z = fmaf(f, w.z, o[q].z);
            o[q].w = fmaf(f, w.w, o[q].w);
        }
    }
    float4* outp = (float4*)&g_bufA[(size_t)i * 32];
    float4* zp   = (float4*)&g_bufB[(size_t)i * 32];
#pragma unroll
    for (int q = 0; q < 8; q++) {
        outp[q] = o[q];
        zp[q]   = make_float4(0.f, 0.f, 0.f, 0.f);
    }
}

// ---------------------------------------------------------------------------
// Scatter layer 2: 8 threads per edge over 32-wide bufA (unchanged, proven).
__global__ void scatter2_kernel(const int* __restrict__ ei, const float* __restrict__ ew, int E) {
    int t = blockIdx.x * blockDim.x + threadIdx.x;
    int e = t >> 3;
    int q = t & 7;
    if (e >= E) return;
    int r = ei[e];
    int c = ei[E + e];
    float nrm = g_dinv[r] * ew[e] * g_dinv[c];
    float4 v = ((const float4*)g_bufA)[(size_t)r * 8 + q];
    float vx = v.x * nrm, vy = v.y * nrm, vz = v.z * nrm, vw = v.w * nrm;
    float4* dst = ((float4*)g_bufB) + (size_t)c * 8 + q;
    asm volatile("red.global.add.v4.f32 [%0], {%1,%2,%3,%4};"
                 :: "l"(dst), "f"(vx), "f"(vy), "f"(vz), "f"(vw)
                 : "memory");
}

// ---------------------------------------------------------------------------
// Final: h2 = relu(agg + dinv^2*xw + b2); out = h2 @ Wfc + bfc
__global__ void final_kernel(const float* __restrict__ b2, const float* __restrict__ Wfc,
                             const float* __restrict__ bfc, float* __restrict__ out, int n) {
    __shared__ float sWfc[32];
    __shared__ float sb2[32];
    __shared__ float sbfc;
    if (threadIdx.x < 32) { sWfc[threadIdx.x] = Wfc[threadIdx.x]; sb2[threadIdx.x] = b2[threadIdx.x]; }
    if (threadIdx.x == 0) sbfc = bfc[0];
    __syncthreads();

    int i = blockIdx.x * blockDim.x + threadIdx.x;
    if (i >= n) return;

    float d = g_dinv[i];
    float s = d * d;
    const float4* aggp = (const float4*)&g_bufB[(size_t)i * 32];
    const float4* xwp  = (const float4*)&g_bufA[(size_t)i * 32];

    float acc = sbfc;
#pragma unroll
    for (int q = 0; q < 8; q++) {
        float4 a  = aggp[q];
        float4 xv = xwp[q];
        acc = fmaf(fmaxf(fmaf(s, xv.x, a.x) + sb2[4 * q + 0], 0.f), sWfc[4 * q + 0], acc);
        acc = fmaf(fmaxf(fmaf(s, xv.y, a.y) + sb2[4 * q + 1], 0.f), sWfc[4 * q + 1], acc);
        acc = fmaf(fmaxf(fmaf(s, xv.z, a.z) + sb2[4 * q + 2], 0.f), sWfc[4 * q + 2], acc);
        acc = fmaf(fmaxf(fmaf(s, xv.w, a.w) + sb2[4 * q + 3], 0.f), sWfc[4 * q + 3], acc);
    }
    out[i] = acc;
}

// ---------------------------------------------------------------------------
extern "C" void kernel_launch(void* const* d_in, const int* in_sizes, int n_in,
                              void* d_out, int out_size) {
    const float* x   = (const float*)d_in[0];
    const float* c   = (const float*)d_in[1];
    const int*   ei  = (const int*)d_in[2];
    const float* ew  = (const float*)d_in[3];
    const float* We1 = (const float*)d_in[4];
    const float* be1 = (const float*)d_in[5];
    const float* We2 = (const float*)d_in[6];
    const float* be2 = (const float*)d_in[7];
    const float* W1  = (const float*)d_in[8];
    const float* b1  = (const float*)d_in[9];
    const float* W2  = (const float*)d_in[10];
    const float* b2  = (const float*)d_in[11];
    const float* Wfc = (const float*)d_in[12];
    const float* bfc = (const float*)d_in[13];

    int n = in_sizes[1] / 2;   // c is [N, 2]
    int E = in_sizes[3];       // ew is [E]
    const int TB = 256;

    zero_kernel <<<(n * 5 + TB - 1) / TB, TB>>>(n);
    int E4 = E / 4;
    deg_kernel  <<<(E4 + TB - 1) / TB, TB>>>(ei + E, ew, E4);
    embed_kernel<<<(n + TB - 1) / TB, TB>>>(x, c, We1, be1, We2, be2, n);
    scatter1_kernel<<<((size_t)E * 5 + TB - 1) / TB, TB>>>(ei, ew, E);   // 20-wide
    mid_kernel  <<<(n + TB - 1) / TB, TB>>>(W1, b1, W2, n);
    scatter2_kernel<<<((size_t)E * 8 + TB - 1) / TB, TB>>>(ei, ew, E);   // 32-wide
    final_kernel<<<(n + TB - 1) / TB, TB>>>(b2, Wfc, bfc, (float*)d_out, n);
}